// round 1
// baseline (speedup 1.0000x reference)
#include <cuda_runtime.h>

#define EPS 1e-4f
#define NDIM 512
#define MAX_ITER 10

__global__ __launch_bounds__(1024, 1)
void sinkhorn_kernel(const float* __restrict__ s,
                     const int* __restrict__ nrows,
                     float* __restrict__ out) {
    __shared__ float r_sh[NDIM];
    __shared__ float c_sh[NDIM];
    __shared__ float red[1024];

    const int b   = blockIdx.x;
    const int tid = threadIdx.x;
    const int n   = nrows[b];
    const float* __restrict__ S = s   + (size_t)b * NDIM * NDIM;
    float* __restrict__       O = out + (size_t)b * NDIM * NDIM;

    if (tid < NDIM) r_sh[tid] = 1.0f;
    __syncthreads();

    for (int it = 0; it < MAX_ITER; ++it) {
        if ((it & 1) == 0) {
            // ---- column step: c[j] = 1 / sum_{i<n} r[i]*(S[i,j]+EPS) ----
            const int j    = tid & (NDIM - 1);
            const int half = tid >> 9;   // 0 or 1: even/odd row slices
            float a0 = 0.f, a1 = 0.f, a2 = 0.f, a3 = 0.f;
            if (j < n) {
                int i = half;
                for (; i + 6 < n; i += 8) {
                    a0 += r_sh[i]     * (S[(size_t)(i)    * NDIM + j] + EPS);
                    a1 += r_sh[i + 2] * (S[(size_t)(i + 2)* NDIM + j] + EPS);
                    a2 += r_sh[i + 4] * (S[(size_t)(i + 4)* NDIM + j] + EPS);
                    a3 += r_sh[i + 6] * (S[(size_t)(i + 6)* NDIM + j] + EPS);
                }
                for (; i < n; i += 2)
                    a0 += r_sh[i] * (S[(size_t)i * NDIM + j] + EPS);
            }
            red[tid] = (a0 + a1) + (a2 + a3);
            __syncthreads();
            if (tid < n)
                c_sh[tid] = 1.0f / (red[tid] + red[tid + NDIM]);
            __syncthreads();
        } else {
            // ---- row step: r[i] = 1 / sum_{j<n} c[j]*(S[i,j]+EPS) ----
            const int wid  = tid >> 5;
            const int lane = tid & 31;
            for (int i = wid; i < n; i += 32) {
                const float* __restrict__ row = S + (size_t)i * NDIM;
                float a0 = 0.f, a1 = 0.f, a2 = 0.f, a3 = 0.f;
                int j = lane;
                for (; j + 96 < n; j += 128) {
                    a0 += c_sh[j]      * (row[j]      + EPS);
                    a1 += c_sh[j + 32] * (row[j + 32] + EPS);
                    a2 += c_sh[j + 64] * (row[j + 64] + EPS);
                    a3 += c_sh[j + 96] * (row[j + 96] + EPS);
                }
                for (; j < n; j += 32)
                    a0 += c_sh[j] * (row[j] + EPS);
                float acc = (a0 + a1) + (a2 + a3);
                #pragma unroll
                for (int o = 16; o; o >>= 1)
                    acc += __shfl_xor_sync(0xffffffffu, acc, o);
                if (lane == 0) r_sh[i] = 1.0f / acc;
            }
            __syncthreads();
        }
    }

    // ---- final fused write: out[i,j] = (S[i,j]+EPS)*r[i]*c[j] inside block, 0 outside ----
    const int nvec = NDIM * NDIM / 4;     // float4 elements per sample
    for (int idx = tid; idx < nvec; idx += 1024) {
        const int i  = idx >> 7;          // 128 float4 per row
        const int j4 = (idx & 127) << 2;
        float4 v = make_float4(0.f, 0.f, 0.f, 0.f);
        if (i < n) {
            const float4 sv = reinterpret_cast<const float4*>(S)[idx];
            const float ri = r_sh[i];
            if (j4 + 3 < n) {
                v.x = (sv.x + EPS) * ri * c_sh[j4];
                v.y = (sv.y + EPS) * ri * c_sh[j4 + 1];
                v.z = (sv.z + EPS) * ri * c_sh[j4 + 2];
                v.w = (sv.w + EPS) * ri * c_sh[j4 + 3];
            } else {
                if (j4     < n) v.x = (sv.x + EPS) * ri * c_sh[j4];
                if (j4 + 1 < n) v.y = (sv.y + EPS) * ri * c_sh[j4 + 1];
                if (j4 + 2 < n) v.z = (sv.z + EPS) * ri * c_sh[j4 + 2];
                if (j4 + 3 < n) v.w = (sv.w + EPS) * ri * c_sh[j4 + 3];
            }
        }
        reinterpret_cast<float4*>(O)[idx] = v;
    }
}

extern "C" void kernel_launch(void* const* d_in, const int* in_sizes, int n_in,
                              void* d_out, int out_size) {
    const float* s     = (const float*)d_in[0];
    const int*   nrows = (const int*)d_in[1];
    float*       out   = (float*)d_out;
    const int B = in_sizes[1];            // nrows has one entry per sample
    sinkhorn_kernel<<<B, 1024>>>(s, nrows, out);
}

// round 2
// speedup vs baseline: 1.4682x; 1.4682x over previous
#include <cuda_runtime.h>

#define EPS 1e-4f
#define NDIM 512
#define MAX_ITER 10

__global__ __launch_bounds__(1024, 1)
void sinkhorn_kernel(const float* __restrict__ s,
                     const int* __restrict__ nrows,
                     float* __restrict__ out) {
    __shared__ __align__(16) float r_sh[NDIM];
    __shared__ __align__(16) float c_sh[NDIM];
    __shared__ __align__(16) float red[8 * NDIM];   // 16 KB column partials
    __shared__ float ssum[32];                      // per-warp partials for scalar sums

    const int b    = blockIdx.x;
    const int tid  = threadIdx.x;
    const int lane = tid & 31;
    const int wid  = tid >> 5;
    const int n    = nrows[b];
    const float* __restrict__ S = s   + (size_t)b * (NDIM * NDIM);
    float* __restrict__       O = out + (size_t)b * (NDIM * NDIM);

    if (tid < NDIM) r_sh[tid] = (tid < n) ? 1.0f : 0.0f;
    float sum_r = (float)n;   // sum of r over active rows (r=1 initially)
    float sum_c = 0.0f;
    __syncthreads();

    const int n_pad8 = (n + 7) & ~7;
    const int npass  = (n + 127) >> 7;   // 128-column passes for the row step

    for (int it = 0; it < MAX_ITER; ++it) {
        if ((it & 1) == 0) {
            // ================= column step: c[j] = 1 / (Σ_i r_i S_ij + EPS*Σr) =====
            const int j4    = (tid & 127) << 2;   // 4-column group
            const int slice = tid >> 7;           // row slice 0..7
            float4 a0 = make_float4(0.f, 0.f, 0.f, 0.f);
            float4 a1 = make_float4(0.f, 0.f, 0.f, 0.f);
            int i = slice;
            for (; i + 8 < n_pad8; i += 16) {
                float4 v0 = *(const float4*)(S + (size_t)i       * NDIM + j4);
                float4 v1 = *(const float4*)(S + (size_t)(i + 8) * NDIM + j4);
                float r0 = r_sh[i], r1 = r_sh[i + 8];
                a0.x = fmaf(r0, v0.x, a0.x); a0.y = fmaf(r0, v0.y, a0.y);
                a0.z = fmaf(r0, v0.z, a0.z); a0.w = fmaf(r0, v0.w, a0.w);
                a1.x = fmaf(r1, v1.x, a1.x); a1.y = fmaf(r1, v1.y, a1.y);
                a1.z = fmaf(r1, v1.z, a1.z); a1.w = fmaf(r1, v1.w, a1.w);
            }
            if (i < n_pad8) {
                float4 v0 = *(const float4*)(S + (size_t)i * NDIM + j4);
                float r0 = r_sh[i];
                a0.x = fmaf(r0, v0.x, a0.x); a0.y = fmaf(r0, v0.y, a0.y);
                a0.z = fmaf(r0, v0.z, a0.z); a0.w = fmaf(r0, v0.w, a0.w);
            }
            a0.x += a1.x; a0.y += a1.y; a0.z += a1.z; a0.w += a1.w;
            *(float4*)(red + slice * NDIM + j4) = a0;
            __syncthreads();

            float cv = 0.0f;
            if (tid < NDIM) {
                float csum = 0.0f;
                #pragma unroll
                for (int ss = 0; ss < 8; ++ss) csum += red[ss * NDIM + tid];
                cv = (tid < n) ? 1.0f / (csum + EPS * sum_r) : 0.0f;
                c_sh[tid] = cv;
            }
            // block-sum of c into sum_c (all threads get the value, no extra barrier)
            float v = cv;
            #pragma unroll
            for (int o = 16; o; o >>= 1) v += __shfl_xor_sync(0xffffffffu, v, o);
            if (lane == 0) ssum[wid] = v;
            __syncthreads();
            sum_c = 0.0f;
            #pragma unroll
            for (int k = 0; k < 16; ++k) sum_c += ssum[k];
        } else {
            // ================= row step: r[i] = 1 / (Σ_j c_j S_ij + EPS*Σc) ========
            const float4* __restrict__ c4 = (const float4*)c_sh;
            int i = wid;
            for (; i + 32 < n; i += 64) {
                const float4* __restrict__ rowA = (const float4*)(S + (size_t)i        * NDIM);
                const float4* __restrict__ rowB = (const float4*)(S + (size_t)(i + 32) * NDIM);
                float4 dA = make_float4(0.f, 0.f, 0.f, 0.f);
                float4 dB = make_float4(0.f, 0.f, 0.f, 0.f);
                for (int p = 0; p < npass; ++p) {
                    const int q = lane + (p << 5);
                    float4 cc = c4[q];
                    float4 vA = rowA[q];
                    float4 vB = rowB[q];
                    dA.x = fmaf(cc.x, vA.x, dA.x); dA.y = fmaf(cc.y, vA.y, dA.y);
                    dA.z = fmaf(cc.z, vA.z, dA.z); dA.w = fmaf(cc.w, vA.w, dA.w);
                    dB.x = fmaf(cc.x, vB.x, dB.x); dB.y = fmaf(cc.y, vB.y, dB.y);
                    dB.z = fmaf(cc.z, vB.z, dB.z); dB.w = fmaf(cc.w, vB.w, dB.w);
                }
                float tA = (dA.x + dA.y) + (dA.z + dA.w);
                float tB = (dB.x + dB.y) + (dB.z + dB.w);
                #pragma unroll
                for (int o = 16; o; o >>= 1) {
                    tA += __shfl_xor_sync(0xffffffffu, tA, o);
                    tB += __shfl_xor_sync(0xffffffffu, tB, o);
                }
                if (lane == 0) {
                    r_sh[i]      = 1.0f / (tA + EPS * sum_c);
                    r_sh[i + 32] = 1.0f / (tB + EPS * sum_c);
                }
            }
            if (i < n) {
                const float4* __restrict__ rowA = (const float4*)(S + (size_t)i * NDIM);
                float4 dA = make_float4(0.f, 0.f, 0.f, 0.f);
                for (int p = 0; p < npass; ++p) {
                    const int q = lane + (p << 5);
                    float4 cc = c4[q];
                    float4 vA = rowA[q];
                    dA.x = fmaf(cc.x, vA.x, dA.x); dA.y = fmaf(cc.y, vA.y, dA.y);
                    dA.z = fmaf(cc.z, vA.z, dA.z); dA.w = fmaf(cc.w, vA.w, dA.w);
                }
                float tA = (dA.x + dA.y) + (dA.z + dA.w);
                #pragma unroll
                for (int o = 16; o; o >>= 1) tA += __shfl_xor_sync(0xffffffffu, tA, o);
                if (lane == 0) r_sh[i] = 1.0f / (tA + EPS * sum_c);
            }
            __syncthreads();
            // block-sum of r into sum_r
            float v = (tid < NDIM) ? r_sh[tid] : 0.0f;
            #pragma unroll
            for (int o = 16; o; o >>= 1) v += __shfl_xor_sync(0xffffffffu, v, o);
            if (lane == 0) ssum[wid] = v;
            __syncthreads();
            sum_r = 0.0f;
            #pragma unroll
            for (int k = 0; k < 16; ++k) sum_r += ssum[k];
        }
    }

    // ============ final fused write: out = (S+EPS)*r*c (zeros encoded in r,c) ======
    const float4* __restrict__ S4 = (const float4*)S;
    const float4* __restrict__ c4 = (const float4*)c_sh;
    float4* __restrict__       O4 = (float4*)O;
    const int nvec = NDIM * NDIM / 4;
    for (int idx = tid; idx < nvec; idx += 1024) {
        const int i = idx >> 7;
        const float ri = r_sh[i];
        float4 v = make_float4(0.f, 0.f, 0.f, 0.f);
        if (ri != 0.0f) {
            float4 sv = S4[idx];
            float4 cc = c4[idx & 127];
            v.x = (sv.x + EPS) * ri * cc.x;
            v.y = (sv.y + EPS) * ri * cc.y;
            v.z = (sv.z + EPS) * ri * cc.z;
            v.w = (sv.w + EPS) * ri * cc.w;
        }
        O4[idx] = v;
    }
}

extern "C" void kernel_launch(void* const* d_in, const int* in_sizes, int n_in,
                              void* d_out, int out_size) {
    const float* s     = (const float*)d_in[0];
    const int*   nrows = (const int*)d_in[1];
    float*       out   = (float*)d_out;
    const int B = in_sizes[1];
    sinkhorn_kernel<<<B, 1024>>>(s, nrows, out);
}

// round 3
// speedup vs baseline: 2.1400x; 1.4576x over previous
#include <cuda_runtime.h>

#define EPS 1e-4f
#define NDIM 512
#define MAX_ITER 10

__device__ __forceinline__ float4 z4f() { return make_float4(0.f, 0.f, 0.f, 0.f); }

__global__ __launch_bounds__(1024, 1)
void sinkhorn_kernel(const float* __restrict__ s,
                     const int* __restrict__ nrows,
                     float* __restrict__ out) {
    extern __shared__ __align__(16) float red[];        // 32*512 floats = 64 KB
    __shared__ __align__(16) float c_sh[NDIM];
    __shared__ float ssumA[32];                          // r-sum partials
    __shared__ float ssumB[32];                          // c-sum partials

    const int b    = blockIdx.x;
    const int tid  = threadIdx.x;
    const int lane = tid & 31;
    const int wid  = tid >> 5;
    const int n    = nrows[b];
    const bool g2  = (n > 256);
    const bool g3  = (n > 384);
    const float* __restrict__ S = s   + (size_t)b * (NDIM * NDIM);
    float* __restrict__       O = out + (size_t)b * (NDIM * NDIM);
    const float4* __restrict__ c4s = (const float4*)c_sh;

    // ======================= iter 0: column pass (r = 1) ========================
    {
        const int j4    = (tid & 127) << 2;
        const int slice = tid >> 7;                      // 0..7
        float4 a0 = z4f(), a1 = z4f();
        if (j4 < n) {
            int i = slice;
            for (; i + 8 < n; i += 16) {
                float4 v0 = *(const float4*)(S + (size_t)i       * NDIM + j4);
                float4 v1 = *(const float4*)(S + (size_t)(i + 8) * NDIM + j4);
                a0.x += v0.x; a0.y += v0.y; a0.z += v0.z; a0.w += v0.w;
                a1.x += v1.x; a1.y += v1.y; a1.z += v1.z; a1.w += v1.w;
            }
            if (i < n) {
                float4 v0 = *(const float4*)(S + (size_t)i * NDIM + j4);
                a0.x += v0.x; a0.y += v0.y; a0.z += v0.z; a0.w += v0.w;
            }
            a0.x += a1.x; a0.y += a1.y; a0.z += a1.z; a0.w += a1.w;
        }
        *(float4*)(red + slice * NDIM + j4) = a0;
        __syncthreads();

        float cv = 0.0f;
        if (tid < n) {
            float cs = 0.0f;
            #pragma unroll
            for (int ss = 0; ss < 8; ++ss) cs += red[ss * NDIM + tid];
            cv = 1.0f / (cs + EPS * (float)n);
        }
        if (tid < NDIM) c_sh[tid] = cv;
        float v = cv;
        #pragma unroll
        for (int o = 16; o; o >>= 1) v += __shfl_xor_sync(0xffffffffu, v, o);
        if (lane == 0) ssumB[wid] = v;
        __syncthreads();
    }
    float sum_c = 0.0f;
    #pragma unroll
    for (int k = 0; k < 32; ++k) sum_c += ssumB[k];

    // ============== 4 fused passes: row(2f+1) + col(2f+2) in one sweep ==========
    #pragma unroll 1
    for (int f = 0; f < 4; ++f) {
        const float eps_c = EPS * sum_c;
        float4 acc0 = z4f(), acc1 = z4f(), acc2 = z4f(), acc3 = z4f();
        float rpart = 0.0f;

        for (int i = wid; i < n; i += 32) {
            const float4* __restrict__ row = (const float4*)(S + (size_t)i * NDIM);
            float4 v0 = row[lane];
            float4 v1 = row[lane + 32];
            float4 v2 = z4f(), v3 = z4f();
            if (g2) v2 = row[lane + 64];
            if (g3) v3 = row[lane + 96];
            float4 c0 = c4s[lane], c1 = c4s[lane + 32];
            float4 c2 = c4s[lane + 64], c3 = c4s[lane + 96];

            float d0 = 0.f, d1 = 0.f, d2 = 0.f, d3 = 0.f;
            d0 = fmaf(v0.x, c0.x, d0); d1 = fmaf(v0.y, c0.y, d1);
            d2 = fmaf(v0.z, c0.z, d2); d3 = fmaf(v0.w, c0.w, d3);
            d0 = fmaf(v1.x, c1.x, d0); d1 = fmaf(v1.y, c1.y, d1);
            d2 = fmaf(v1.z, c1.z, d2); d3 = fmaf(v1.w, c1.w, d3);
            d0 = fmaf(v2.x, c2.x, d0); d1 = fmaf(v2.y, c2.y, d1);
            d2 = fmaf(v2.z, c2.z, d2); d3 = fmaf(v2.w, c2.w, d3);
            d0 = fmaf(v3.x, c3.x, d0); d1 = fmaf(v3.y, c3.y, d1);
            d2 = fmaf(v3.z, c3.z, d2); d3 = fmaf(v3.w, c3.w, d3);
            float t = (d0 + d1) + (d2 + d3);
            #pragma unroll
            for (int o = 16; o; o >>= 1) t += __shfl_xor_sync(0xffffffffu, t, o);

            const float ri = 1.0f / (t + eps_c);
            rpart += ri;

            acc0.x = fmaf(ri, v0.x, acc0.x); acc0.y = fmaf(ri, v0.y, acc0.y);
            acc0.z = fmaf(ri, v0.z, acc0.z); acc0.w = fmaf(ri, v0.w, acc0.w);
            acc1.x = fmaf(ri, v1.x, acc1.x); acc1.y = fmaf(ri, v1.y, acc1.y);
            acc1.z = fmaf(ri, v1.z, acc1.z); acc1.w = fmaf(ri, v1.w, acc1.w);
            acc2.x = fmaf(ri, v2.x, acc2.x); acc2.y = fmaf(ri, v2.y, acc2.y);
            acc2.z = fmaf(ri, v2.z, acc2.z); acc2.w = fmaf(ri, v2.w, acc2.w);
            acc3.x = fmaf(ri, v3.x, acc3.x); acc3.y = fmaf(ri, v3.y, acc3.y);
            acc3.z = fmaf(ri, v3.z, acc3.z); acc3.w = fmaf(ri, v3.w, acc3.w);
        }

        float4* __restrict__ rw = (float4*)(red + wid * NDIM);
        rw[lane]      = acc0;
        rw[lane + 32] = acc1;
        rw[lane + 64] = acc2;
        rw[lane + 96] = acc3;
        if (lane == 0) ssumA[wid] = rpart;   // warp-uniform value
        __syncthreads();

        float sum_r = 0.0f;
        #pragma unroll
        for (int k = 0; k < 32; ++k) sum_r += ssumA[k];

        float cv = 0.0f;
        if (tid < n) {
            float cs = 0.0f;
            #pragma unroll
            for (int w = 0; w < 32; ++w) cs += red[w * NDIM + tid];
            cv = 1.0f / (cs + EPS * sum_r);
        }
        if (tid < NDIM) c_sh[tid] = cv;
        float v = cv;
        #pragma unroll
        for (int o = 16; o; o >>= 1) v += __shfl_xor_sync(0xffffffffu, v, o);
        if (lane == 0) ssumB[wid] = v;
        __syncthreads();
        sum_c = 0.0f;
        #pragma unroll
        for (int k = 0; k < 32; ++k) sum_c += ssumB[k];
    }

    // ============== final pass: row step (iter 9) fused with output write =======
    {
        const float eps_c = EPS * sum_c;
        for (int i = wid; i < n; i += 32) {
            const float4* __restrict__ row = (const float4*)(S + (size_t)i * NDIM);
            float4* __restrict__ orow = (float4*)(O + (size_t)i * NDIM);
            float4 v0 = row[lane];
            float4 v1 = row[lane + 32];
            float4 v2 = row[lane + 64];
            float4 v3 = row[lane + 96];
            float4 c0 = c4s[lane], c1 = c4s[lane + 32];
            float4 c2 = c4s[lane + 64], c3 = c4s[lane + 96];

            float d0 = 0.f, d1 = 0.f, d2 = 0.f, d3 = 0.f;
            d0 = fmaf(v0.x, c0.x, d0); d1 = fmaf(v0.y, c0.y, d1);
            d2 = fmaf(v0.z, c0.z, d2); d3 = fmaf(v0.w, c0.w, d3);
            d0 = fmaf(v1.x, c1.x, d0); d1 = fmaf(v1.y, c1.y, d1);
            d2 = fmaf(v1.z, c1.z, d2); d3 = fmaf(v1.w, c1.w, d3);
            d0 = fmaf(v2.x, c2.x, d0); d1 = fmaf(v2.y, c2.y, d1);
            d2 = fmaf(v2.z, c2.z, d2); d3 = fmaf(v2.w, c2.w, d3);
            d0 = fmaf(v3.x, c3.x, d0); d1 = fmaf(v3.y, c3.y, d1);
            d2 = fmaf(v3.z, c3.z, d2); d3 = fmaf(v3.w, c3.w, d3);
            float t = (d0 + d1) + (d2 + d3);
            #pragma unroll
            for (int o = 16; o; o >>= 1) t += __shfl_xor_sync(0xffffffffu, t, o);
            const float ri = 1.0f / (t + eps_c);

            float4 w;
            w.x = (v0.x + EPS) * ri * c0.x; w.y = (v0.y + EPS) * ri * c0.y;
            w.z = (v0.z + EPS) * ri * c0.z; w.w = (v0.w + EPS) * ri * c0.w;
            orow[lane] = w;
            w.x = (v1.x + EPS) * ri * c1.x; w.y = (v1.y + EPS) * ri * c1.y;
            w.z = (v1.z + EPS) * ri * c1.z; w.w = (v1.w + EPS) * ri * c1.w;
            orow[lane + 32] = w;
            w.x = (v2.x + EPS) * ri * c2.x; w.y = (v2.y + EPS) * ri * c2.y;
            w.z = (v2.z + EPS) * ri * c2.z; w.w = (v2.w + EPS) * ri * c2.w;
            orow[lane + 64] = w;
            w.x = (v3.x + EPS) * ri * c3.x; w.y = (v3.y + EPS) * ri * c3.y;
            w.z = (v3.z + EPS) * ri * c3.z; w.w = (v3.w + EPS) * ri * c3.w;
            orow[lane + 96] = w;
        }
        // zero-fill rows i >= n
        float4* __restrict__ O4 = (float4*)O;
        const float4 z = z4f();
        for (int idx = n * 128 + tid; idx < NDIM * 128; idx += 1024) O4[idx] = z;
    }
}

extern "C" void kernel_launch(void* const* d_in, const int* in_sizes, int n_in,
                              void* d_out, int out_size) {
    const float* s     = (const float*)d_in[0];
    const int*   nrows = (const int*)d_in[1];
    float*       out   = (float*)d_out;
    const int B = in_sizes[1];
    const int shbytes = 32 * NDIM * sizeof(float);   // 64 KB dynamic
    static bool attr_set = false;
    if (!attr_set) {
        cudaFuncSetAttribute(sinkhorn_kernel,
                             cudaFuncAttributeMaxDynamicSharedMemorySize, shbytes);
        attr_set = true;
    }
    sinkhorn_kernel<<<B, 1024, shbytes>>>(s, nrows, out);
}